// round 8
// baseline (speedup 1.0000x reference)
#include <cuda_runtime.h>
#include <math.h>

// Problem dims
#define T_STEPS 8
#define N_PED   2048
#define H_DIM   128
#define D_IN    64
#define G4H     512   // 4*H
#define N_GRP   64
#define GRP_N   32
#define DD_DIM  64
#define NH      4

typedef unsigned long long ull;

// packed f32x2 helpers (sm_100+)
#define FMA2(d, a, b, c) asm("fma.rn.f32x2 %0, %1, %2, %3;" : "=l"(d) : "l"(a), "l"(b), "l"(c))
#define PK2(dst, s) do { unsigned _u = __float_as_uint(s); \
    asm("mov.b64 %0, {%1, %1};" : "=l"(dst) : "r"(_u)); } while (0)
#define PKAB(dst, a, b) do { unsigned _ua = __float_as_uint(a), _ub = __float_as_uint(b); \
    asm("mov.b64 %0, {%1, %2};" : "=l"(dst) : "r"(_ua), "r"(_ub)); } while (0)
#define UNPK2(lo, hi, v) do { unsigned _a, _b; \
    asm("mov.b64 {%0, %1}, %2;" : "=r"(_a), "=r"(_b) : "l"(v)); \
    lo = __uint_as_float(_a); hi = __uint_as_float(_b); } while (0)

// ---------------- scratch (device globals; no allocation) ----------------
// Weight layout: d_wt2[k][ch][u] with u in (i,f,g,o): one LDG.128 per (k,ch).
__device__ __align__(16) float d_wt2 [H_DIM * G4H];
__device__ __align__(16) float d_wit2[D_IN * G4H];
__device__ __align__(16) float d_bsum2[G4H];          // [ch][u]
__device__ __align__(16) float d_h [N_PED * H_DIM];
__device__ __align__(16) float d_th[N_PED * H_DIM];   // tanh(h)
__device__ __align__(16) float d_uv[2 * NH * H_DIM];  // u then v
__device__ __align__(16) float d_gate[N_PED * GRP_N * H_DIM];  // gate[p][j][c]
__device__ __align__(16) float d_m [N_PED * G4H];     // m_cat[p][h*128+f]

// ---------------- fast activations ----------------
__device__ __forceinline__ float sigf(float x) {
    return __fdividef(1.f, 1.f + __expf(-x));
}
__device__ __forceinline__ float tanh_f(float x) {
    return 1.f - __fdividef(2.f, __expf(2.f * x) + 1.f);
}

// ---------------- weight prep: permute to [k][ch][u] + bias sum ----------------
__global__ void prep_kernel(const float* __restrict__ W_hh, const float* __restrict__ W_ih,
                            const float* __restrict__ b_ih, const float* __restrict__ b_hh)
{
    int i = blockIdx.x * 256 + threadIdx.x;
    if (i < H_DIM * G4H) {
        int k = i >> 9, q = i & 511;
        int ch = q >> 2, u = q & 3;
        d_wt2[i] = W_hh[(u * 128 + ch) * H_DIM + k];
        return;
    }
    int j = i - H_DIM * G4H;
    if (j < D_IN * G4H) {
        int k = j >> 9, q = j & 511;
        int ch = q >> 2, u = q & 3;
        d_wit2[j] = W_ih[(u * 128 + ch) * D_IN + k];
        return;
    }
    int b = j - D_IN * G4H;
    if (b < G4H) {
        int ch = b >> 2, u = b & 3;
        int n = u * 128 + ch;
        d_bsum2[b] = b_ih[n] + b_hh[n];
    }
}

// ---------------- u_h = w_h @ a1, v_h = w_h @ a2 (1 warp per dot) ----------------
__global__ void uv_kernel(const float* __restrict__ gat_w,
                          const float* __restrict__ gat_a)
{
    int w = (blockIdx.x << 2) + (threadIdx.x >> 5);   // 0..1023
    int lane = threadIdx.x & 31;
    int sel = w >> 9;
    int h   = (w >> 7) & 3;
    int c   = w & 127;
    const float* a  = gat_a + sel * H_DIM;
    const float* wp = gat_w + ((size_t)h * H_DIM + c) * H_DIM;
    float s = 0.f;
#pragma unroll
    for (int o = lane; o < H_DIM; o += 32) s = fmaf(wp[o], a[o], s);
#pragma unroll
    for (int o = 16; o; o >>= 1) s += __shfl_xor_sync(0xffffffffu, s, o);
    if (lane == 0) d_uv[sel * (NH * H_DIM) + h * H_DIM + c] = s;
}

// ---------------- fused embed + 8-step LSTM: 512 threads, dup-operand smem ----------------
// ch = tid&127 owns channel ch (all 4 gates); ty = tid>>7 owns peds 4ty..4ty+3.
// h and x live in smem as value-duplicated f32x2 (ull per ped):
// per k the inner loop is 1 LDG.128 (weights) + 2 LDS.128 (4 peds) + 8 FMA2, no movs.
#define HP 18   // h row pitch in ull (16B-aligned, de-conflicts epilogue STS.64)
__global__ __launch_bounds__(512) void lstm512(
    const float* __restrict__ h0, const float* __restrict__ c0,
    const float* __restrict__ obs,
    const float* __restrict__ W_emb, const float* __restrict__ b_emb)
{
    extern __shared__ __align__(16) char sraw[];
    ull (*h_dup)[H_DIM][HP] = (ull (*)[H_DIM][HP])sraw;                  // 2*128*18*8 = 36 KB
    ull (*x_dup)[D_IN][16]  = (ull (*)[D_IN][16])(sraw + 2 * H_DIM * HP * 8); // 8*64*16*8 = 64 KB

    int tid = threadIdx.x;
    int ch = tid & 127, ty = tid >> 7;
    int p0 = blockIdx.x * 16;

    // embed x (duplicated): consecutive tid -> consecutive ped (2-way STS)
    for (int i = tid; i < T_STEPS * 16 * D_IN; i += 512) {
        int r = i & 15;
        int c = (i >> 4) & 63;
        int t = i >> 10;
        const float* op = obs + ((size_t)t * N_PED + p0 + r) * 2;
        float v = fmaxf(fmaf(op[0], W_emb[c], fmaf(op[1], W_emb[64 + c], b_emb[c])), 0.f);
        ull dv; PKAB(dv, v, v);
        x_dup[t][c][r] = dv;
    }
    // stage h0 (duplicated)
    for (int i = tid; i < 16 * H_DIM; i += 512) {
        int r = i & 15;
        int k = i >> 4;
        float v = h0[(size_t)(p0 + r) * H_DIM + k];
        ull dv; PKAB(dv, v, v);
        h_dup[0][k][r] = dv;
    }
    // c in registers (4 peds, 1 channel)
    float c_reg[4];
#pragma unroll
    for (int p = 0; p < 4; p++)
        c_reg[p] = c0[(size_t)(p0 + 4 * ty + p) * H_DIM + ch];
    ulonglong2 bi = *(const ulonglong2*)&d_bsum2[ch * 4];
    __syncthreads();

    const ulonglong2* wt2 = (const ulonglong2*)d_wt2;   // idx k*128 + ch
    const ulonglong2* wi2 = (const ulonglong2*)d_wit2;

    for (int t = 0; t < T_STEPS; t++) {
        int cur = t & 1, nxt = cur ^ 1;
        ull acc[4][2];
#pragma unroll
        for (int p = 0; p < 4; p++) { acc[p][0] = bi.x; acc[p][1] = bi.y; }
        // recurrent: K = 128
#pragma unroll 8
        for (int k = 0; k < H_DIM; k++) {
            ulonglong2 wv = wt2[k * 128 + ch];
            ulonglong2 h01 = *(const ulonglong2*)&h_dup[cur][k][4 * ty];
            ulonglong2 h23 = *(const ulonglong2*)&h_dup[cur][k][4 * ty + 2];
            FMA2(acc[0][0], h01.x, wv.x, acc[0][0]);
            FMA2(acc[0][1], h01.x, wv.y, acc[0][1]);
            FMA2(acc[1][0], h01.y, wv.x, acc[1][0]);
            FMA2(acc[1][1], h01.y, wv.y, acc[1][1]);
            FMA2(acc[2][0], h23.x, wv.x, acc[2][0]);
            FMA2(acc[2][1], h23.x, wv.y, acc[2][1]);
            FMA2(acc[3][0], h23.y, wv.x, acc[3][0]);
            FMA2(acc[3][1], h23.y, wv.y, acc[3][1]);
        }
        // input: K = 64
#pragma unroll 8
        for (int k = 0; k < D_IN; k++) {
            ulonglong2 wv = wi2[k * 128 + ch];
            ulonglong2 x01 = *(const ulonglong2*)&x_dup[t][k][4 * ty];
            ulonglong2 x23 = *(const ulonglong2*)&x_dup[t][k][4 * ty + 2];
            FMA2(acc[0][0], x01.x, wv.x, acc[0][0]);
            FMA2(acc[0][1], x01.x, wv.y, acc[0][1]);
            FMA2(acc[1][0], x01.y, wv.x, acc[1][0]);
            FMA2(acc[1][1], x01.y, wv.y, acc[1][1]);
            FMA2(acc[2][0], x23.x, wv.x, acc[2][0]);
            FMA2(acc[2][1], x23.x, wv.y, acc[2][1]);
            FMA2(acc[3][0], x23.y, wv.x, acc[3][0]);
            FMA2(acc[3][1], x23.y, wv.y, acc[3][1]);
        }
        // epilogue writes the OTHER h buffer: no barrier needed before it
#pragma unroll
        for (int p = 0; p < 4; p++) {
            float iv, fv, gv, ov;
            UNPK2(iv, fv, acc[p][0]);
            UNPK2(gv, ov, acc[p][1]);
            float cn = sigf(fv) * c_reg[p] + sigf(iv) * tanh_f(gv);
            c_reg[p] = cn;
            float hv = sigf(ov) * tanh_f(cn);
            ull dv; PKAB(dv, hv, hv);
            h_dup[nxt][ch][4 * ty + p] = dv;
        }
        __syncthreads();   // writers done before next step's reads
    }
    // final h in buffer (T_STEPS & 1) = 0
    for (int i = tid; i < 16 * H_DIM; i += 512) {
        int k = i & 127;
        int r = i >> 7;
        float v = (float)__uint_as_float((unsigned)(h_dup[0][k][r] & 0xffffffffull));
        d_h [(size_t)(p0 + r) * H_DIM + k] = v;
        d_th[(size_t)(p0 + r) * H_DIM + k] = tanh_f(v);
    }
}

// ---------------- gate MLP (position-only), standalone ----------------
__global__ __launch_bounds__(256) void gateMLP(
    const float* __restrict__ goal, const float* __restrict__ action,
    const float* __restrict__ W_dist, const float* __restrict__ b_dist,
    const float* __restrict__ W_gate, const float* __restrict__ b_gate)
{
    __shared__ __align__(16) float t_sh[GRP_N * DD_DIM];       // 8KB
    __shared__ __align__(16) float s_sh[2 * DD_DIM];
    __shared__ __align__(16) float r_sh[2 * GRP_N * DD_DIM];   // 16KB
    __shared__ float pax[GRP_N], pay[GRP_N], pgx[GRP_N], pgy[GRP_N];

    int tid = threadIdx.x;
    int b = blockIdx.x;
    int g  = b >> 4;
    int ip = b & 15;
    int half = tid >> 7;
    int c    = tid & 127;
    int i_loc = 2 * ip + half;
    int p = g * GRP_N + i_loc;

    if (tid < GRP_N) {
        int q = g * GRP_N + tid;
        pax[tid] = action[q * 2 + 0]; pay[tid] = action[q * 2 + 1];
        pgx[tid] = goal[q * 2 + 0];   pgy[tid] = goal[q * 2 + 1];
    }
    __syncthreads();
    for (int idx = tid; idx < GRP_N * DD_DIM; idx += 256) {
        int j = idx >> 6, d = idx & 63;
        float t = fmaf(pax[j], W_dist[4 * 64 + d],
                  fmaf(pay[j], W_dist[5 * 64 + d],
                  fmaf(pgx[j], W_dist[6 * 64 + d],
                       pgy[j] * W_dist[7 * 64 + d])));
        t_sh[idx] = t;
    }
    if (tid < 2 * DD_DIM) {
        int hh = tid >> 6, d = tid & 63;
        int il = 2 * ip + hh;
        float s = b_dist[d];
        s = fmaf(pax[il], W_dist[0 * 64 + d], s);
        s = fmaf(pay[il], W_dist[1 * 64 + d], s);
        s = fmaf(pgx[il], W_dist[2 * 64 + d], s);
        s = fmaf(pgy[il], W_dist[3 * 64 + d], s);
        s_sh[tid] = s;
    }
    __syncthreads();
    for (int idx = tid; idx < 2 * GRP_N * DD_DIM; idx += 256) {
        int hh = idx >> 11, jd = idx & 2047;
        r_sh[idx] = fmaxf(s_sh[hh * 64 + (jd & 63)] + t_sh[jd], 0.f);
    }
    __syncthreads();

    float bg = b_gate[c];
    const float* rbase = r_sh + half * GRP_N * DD_DIM;
    float* gout = d_gate + (size_t)p * GRP_N * H_DIM;
#pragma unroll
    for (int jt = 0; jt < 4; jt++) {
        int j0 = jt * 8;
        ull acc2[8];
#pragma unroll
        for (int jj = 0; jj < 8; jj++) acc2[jj] = 0ull;
        for (int d0 = 0; d0 < DD_DIM; d0 += 4) {
            float w0 = W_gate[(d0 + 0) * H_DIM + c];
            float w1 = W_gate[(d0 + 1) * H_DIM + c];
            float w2 = W_gate[(d0 + 2) * H_DIM + c];
            float w3 = W_gate[(d0 + 3) * H_DIM + c];
            ull ww0, ww1;
            PKAB(ww0, w0, w1);
            PKAB(ww1, w2, w3);
#pragma unroll
            for (int jj = 0; jj < 8; jj++) {
                ulonglong2 rv = *(const ulonglong2*)&rbase[(j0 + jj) * DD_DIM + d0];
                FMA2(acc2[jj], rv.x, ww0, acc2[jj]);
                FMA2(acc2[jj], rv.y, ww1, acc2[jj]);
            }
        }
#pragma unroll
        for (int jj = 0; jj < 8; jj++) {
            float lo, hi;
            UNPK2(lo, hi, acc2[jj]);
            gout[(j0 + jj) * H_DIM + c] = sigf(lo + hi + bg);
        }
    }
}

// ---------------- KERNEL B: h-dependent GAT ----------------
__global__ __launch_bounds__(256) void gatB(const float* __restrict__ goal_hidden)
{
    __shared__ __align__(16) float gth[2 * GRP_N * H_DIM];  // 32KB
    __shared__ float ah_sh[2][H_DIM];
    __shared__ float sdot[2][NH][GRP_N];
    __shared__ float alpha[2][NH][GRP_N + 1];
    __shared__ float hsu[2][NH], hsv[2][NH];

    int tid = threadIdx.x;
    int b = blockIdx.x;
    int g  = b >> 4;
    int ip = b & 15;
    int half = tid >> 7;
    int c    = tid & 127;
    int i_loc = 2 * ip + half;
    int p = g * GRP_N + i_loc;

    float ahc = d_h[(size_t)p * H_DIM + c];
    float ghc = goal_hidden[(size_t)p * H_DIM + c];
    ah_sh[half][c] = ahc;

    {
        const float* gp = d_gate + (size_t)p * GRP_N * H_DIM;
        float* dst = gth + half * GRP_N * H_DIM;
#pragma unroll 4
        for (int j = 0; j < GRP_N; j++) {
            float v = gp[j * H_DIM + c] * d_th[(size_t)(g * GRP_N + j) * H_DIM + c];
            dst[j * H_DIM + c] = (j == i_loc) ? ghc : v;
        }
    }
    __syncthreads();

    {
        int t128 = tid & 127, w = t128 >> 5, lane = t128 & 31;
        const float* uh = d_uv + w * H_DIM;
        const float* vh = d_uv + NH * H_DIM + w * H_DIM;
        float u4[4], v4[4], a4[4];
#pragma unroll
        for (int k = 0; k < 4; k++) {
            int cc = lane + 32 * k;
            u4[k] = uh[cc]; v4[k] = vh[cc];
            a4[k] = ah_sh[half][cc];
        }
        float su = 0.f, sv = 0.f;
#pragma unroll
        for (int k = 0; k < 4; k++) { su = fmaf(a4[k], u4[k], su); sv = fmaf(a4[k], v4[k], sv); }
#pragma unroll
        for (int o = 16; o; o >>= 1) {
            su += __shfl_xor_sync(0xffffffffu, su, o);
            sv += __shfl_xor_sync(0xffffffffu, sv, o);
        }
        if (lane == 0) { hsu[half][w] = su; hsv[half][w] = sv; }
        const float* src = gth + half * GRP_N * H_DIM;
        for (int j = 0; j < GRP_N; j++) {
            float s = 0.f;
#pragma unroll
            for (int k = 0; k < 4; k++)
                s = fmaf(src[j * H_DIM + lane + 32 * k], v4[k], s);
#pragma unroll
            for (int o = 16; o; o >>= 1) s += __shfl_xor_sync(0xffffffffu, s, o);
            if (lane == 0) sdot[half][w][j] = s;
        }
    }
    __syncthreads();

    if (tid < 8) {
        int hh = tid >> 2, h = tid & 3;
        float su = hsu[hh][h], sv = hsv[hh][h];
        float sc[GRP_N + 1];
        float s0 = su + sv;
        sc[0] = (s0 >= 0.f) ? s0 : 0.2f * s0;
        float mx = sc[0];
#pragma unroll
        for (int j = 0; j < GRP_N; j++) {
            float s = su + sdot[hh][h][j];
            s = (s >= 0.f) ? s : 0.2f * s;
            sc[j + 1] = s;
            mx = fmaxf(mx, s);
        }
        float sum = 0.f;
#pragma unroll
        for (int k = 0; k <= GRP_N; k++) { sc[k] = __expf(sc[k] - mx); sum += sc[k]; }
        float inv = __fdividef(1.f, sum);
#pragma unroll
        for (int k = 0; k <= GRP_N; k++) alpha[hh][h][k] = sc[k] * inv;
    }
    __syncthreads();

    // m_cat[p][h*128+c]
    {
        float macc[NH];
#pragma unroll
        for (int h = 0; h < NH; h++) macc[h] = alpha[half][h][0] * ahc;
        const float* src = gth + half * GRP_N * H_DIM;
#pragma unroll 4
        for (int j = 0; j < GRP_N; j++) {
            float gval = src[j * H_DIM + c];
#pragma unroll
            for (int h = 0; h < NH; h++)
                macc[h] = fmaf(alpha[half][h][j + 1], gval, macc[h]);
        }
#pragma unroll
        for (int h = 0; h < NH; h++)
            d_m[(size_t)p * G4H + h * H_DIM + c] = macc[h];
    }
}

// ---------------- g3: out = relu(0.25 * m_cat @ w_cat) + bias ----------------
__global__ __launch_bounds__(256) void g3_kernel(
    const float* __restrict__ gat_w, const float* __restrict__ gat_bias,
    float* __restrict__ out)
{
    __shared__ __align__(16) float m_sh[16][G4H];   // 32KB
    int tid = threadIdx.x;
    int tx = tid & 63, ty = tid >> 6;
    int p0 = blockIdx.x * 16;

    {
        float4* dst = (float4*)&m_sh[0][0];
        const float4* src = (const float4*)&d_m[(size_t)p0 * G4H];
        for (int i = tid; i < 2048; i += 256) dst[i] = src[i];
    }
    __syncthreads();

    ull acc[4];
#pragma unroll
    for (int p = 0; p < 4; p++) acc[p] = 0ull;
#pragma unroll 8
    for (int k = 0; k < G4H; k++) {
        ull wv = *(const ull*)&gat_w[(size_t)k * H_DIM + 2 * tx];
        ull mp[4];
#pragma unroll
        for (int p = 0; p < 4; p++) PK2(mp[p], m_sh[4 * ty + p][k]);
#pragma unroll
        for (int p = 0; p < 4; p++) FMA2(acc[p], mp[p], wv, acc[p]);
    }
    float b0 = gat_bias[2 * tx], b1 = gat_bias[2 * tx + 1];
#pragma unroll
    for (int p = 0; p < 4; p++) {
        float lo, hi;
        UNPK2(lo, hi, acc[p]);
        float2 o2;
        o2.x = fmaxf(0.25f * lo, 0.f) + b0;
        o2.y = fmaxf(0.25f * hi, 0.f) + b1;
        *(float2*)&out[(size_t)(p0 + 4 * ty + p) * H_DIM + 2 * tx] = o2;
    }
}

// ---------------- host ----------------
extern "C" void kernel_launch(void* const* d_in, const int* in_sizes, int n_in,
                              void* d_out, int out_size)
{
    const float* obs         = (const float*)d_in[0];
    const float* goal_hidden = (const float*)d_in[1];
    const float* goal        = (const float*)d_in[2];
    const float* action      = (const float*)d_in[3];
    const float* h0          = (const float*)d_in[4];
    const float* c0          = (const float*)d_in[5];
    const float* W_emb       = (const float*)d_in[6];
    const float* b_emb       = (const float*)d_in[7];
    const float* W_ih        = (const float*)d_in[8];
    const float* W_hh        = (const float*)d_in[9];
    const float* b_ih        = (const float*)d_in[10];
    const float* b_hh        = (const float*)d_in[11];
    const float* W_dist      = (const float*)d_in[12];
    const float* b_dist      = (const float*)d_in[13];
    const float* W_gate      = (const float*)d_in[14];
    const float* b_gate      = (const float*)d_in[15];
    const float* gat_w       = (const float*)d_in[16];
    const float* gat_a       = (const float*)d_in[17];
    const float* gat_bias    = (const float*)d_in[18];
    float* out = (float*)d_out;

    const int LSTM_SMEM = 2 * H_DIM * HP * 8 + T_STEPS * D_IN * 16 * 8;  // 36KB + 64KB
    cudaFuncSetAttribute(lstm512, cudaFuncAttributeMaxDynamicSharedMemorySize, LSTM_SMEM);

    {
        int total = H_DIM * G4H + D_IN * G4H + G4H;
        prep_kernel<<<(total + 255) / 256, 256>>>(W_hh, W_ih, b_ih, b_hh);
    }
    uv_kernel<<<256, 128>>>(gat_w, gat_a);
    gateMLP<<<1024, 256>>>(goal, action, W_dist, b_dist, W_gate, b_gate);

    lstm512<<<N_PED / 16, 512, LSTM_SMEM>>>(h0, c0, obs, W_emb, b_emb);

    gatB<<<1024, 256>>>(goal_hidden);
    g3_kernel<<<N_PED / 16, 256>>>(gat_w, gat_bias, out);
}

// round 9
// speedup vs baseline: 1.0180x; 1.0180x over previous
#include <cuda_runtime.h>
#include <math.h>

// Problem dims
#define T_STEPS 8
#define N_PED   2048
#define H_DIM   128
#define D_IN    64
#define G4H     512   // 4*H
#define N_GRP   64
#define GRP_N   32
#define DD_DIM  64
#define NH      4

typedef unsigned long long ull;

// packed f32x2 helpers (sm_100+)
#define FMA2(d, a, b, c) asm("fma.rn.f32x2 %0, %1, %2, %3;" : "=l"(d) : "l"(a), "l"(b), "l"(c))
#define ADD2(d, a, b) asm("add.rn.f32x2 %0, %1, %2;" : "=l"(d) : "l"(a), "l"(b))
#define PK2(dst, s) do { unsigned _u = __float_as_uint(s); \
    asm("mov.b64 %0, {%1, %1};" : "=l"(dst) : "r"(_u)); } while (0)
#define PKAB(dst, a, b) do { unsigned _ua = __float_as_uint(a), _ub = __float_as_uint(b); \
    asm("mov.b64 %0, {%1, %2};" : "=l"(dst) : "r"(_ua), "r"(_ub)); } while (0)
#define UNPK2(lo, hi, v) do { unsigned _a, _b; \
    asm("mov.b64 {%0, %1}, %2;" : "=r"(_a), "=r"(_b) : "l"(v)); \
    lo = __uint_as_float(_a); hi = __uint_as_float(_b); } while (0)

// ---------------- scratch (device globals; no allocation) ----------------
// Weight layout: d_wt2[k][ch][u] with u in (i,f,g,o): one LDG.128 per (k,ch).
__device__ __align__(16) float d_wt2 [H_DIM * G4H];
__device__ __align__(16) float d_wit2[D_IN * G4H];
__device__ __align__(16) float d_bsum2[G4H];          // [ch][u]
__device__ __align__(16) float d_h [N_PED * H_DIM];
__device__ __align__(16) float d_th[N_PED * H_DIM];   // tanh(h)
__device__ __align__(16) float d_uv[2 * NH * H_DIM];  // u then v
__device__ __align__(16) float d_gate[N_PED * GRP_N * H_DIM];  // gate[p][j][c]
__device__ __align__(16) float d_m [N_PED * G4H];     // m_cat[p][h*128+f]

// ---------------- fast activations ----------------
__device__ __forceinline__ float sigf(float x) {
    return __fdividef(1.f, 1.f + __expf(-x));
}
__device__ __forceinline__ float tanh_f(float x) {
    return 1.f - __fdividef(2.f, __expf(2.f * x) + 1.f);
}

// ---------------- weight prep: permute to [k][ch][u] + bias sum ----------------
__global__ void prep_kernel(const float* __restrict__ W_hh, const float* __restrict__ W_ih,
                            const float* __restrict__ b_ih, const float* __restrict__ b_hh)
{
    int i = blockIdx.x * 256 + threadIdx.x;
    if (i < H_DIM * G4H) {
        int k = i >> 9, q = i & 511;
        int ch = q >> 2, u = q & 3;
        d_wt2[i] = W_hh[(u * 128 + ch) * H_DIM + k];
        return;
    }
    int j = i - H_DIM * G4H;
    if (j < D_IN * G4H) {
        int k = j >> 9, q = j & 511;
        int ch = q >> 2, u = q & 3;
        d_wit2[j] = W_ih[(u * 128 + ch) * D_IN + k];
        return;
    }
    int b = j - D_IN * G4H;
    if (b < G4H) {
        int ch = b >> 2, u = b & 3;
        int n = u * 128 + ch;
        d_bsum2[b] = b_ih[n] + b_hh[n];
    }
}

// ---------------- u_h = w_h @ a1, v_h = w_h @ a2 (1 warp per dot) ----------------
__global__ void uv_kernel(const float* __restrict__ gat_w,
                          const float* __restrict__ gat_a)
{
    int w = (blockIdx.x << 2) + (threadIdx.x >> 5);   // 0..1023
    int lane = threadIdx.x & 31;
    int sel = w >> 9;
    int h   = (w >> 7) & 3;
    int c   = w & 127;
    const float* a  = gat_a + sel * H_DIM;
    const float* wp = gat_w + ((size_t)h * H_DIM + c) * H_DIM;
    float s = 0.f;
#pragma unroll
    for (int o = lane; o < H_DIM; o += 32) s = fmaf(wp[o], a[o], s);
#pragma unroll
    for (int o = 16; o; o >>= 1) s += __shfl_xor_sync(0xffffffffu, s, o);
    if (lane == 0) d_uv[sel * (NH * H_DIM) + h * H_DIM + c] = s;
}

// ---------------- fused embed + 8-step LSTM: 1024 threads, split-K ----------------
// ch = tid&127 (channel, all 4 gates), ty = (tid>>7)&3 (peds 4ty..4ty+3),
// kh = tid>>9 (K-half). Partial gate sums combined via smem + add.rn.f32x2;
// kh=0 threads run the epilogue. 32 warps/SM for latency hiding.
#define HP 18   // h row pitch in ull
__global__ __launch_bounds__(1024, 1) void lstm1024(
    const float* __restrict__ h0, const float* __restrict__ c0,
    const float* __restrict__ obs,
    const float* __restrict__ W_emb, const float* __restrict__ b_emb)
{
    extern __shared__ __align__(16) char sraw[];
    ull (*h_dup)[H_DIM][HP] = (ull (*)[H_DIM][HP])sraw;                   // 36 KB
    ull (*x_dup)[D_IN][16]  = (ull (*)[D_IN][16])(sraw + 36864);          // 64 KB
    ull (*red)[512]         = (ull (*)[512])(sraw + 36864 + 65536);       // 32 KB

    int tid = threadIdx.x;
    int ch = tid & 127;
    int ty = (tid >> 7) & 3;
    int kh = tid >> 9;
    int p0 = blockIdx.x * 16;

    // embed x (duplicated f32x2 per ped)
    for (int i = tid; i < T_STEPS * 16 * D_IN; i += 1024) {
        int r = i & 15;
        int c = (i >> 4) & 63;
        int t = i >> 10;
        const float* op = obs + ((size_t)t * N_PED + p0 + r) * 2;
        float v = fmaxf(fmaf(op[0], W_emb[c], fmaf(op[1], W_emb[64 + c], b_emb[c])), 0.f);
        ull dv; PKAB(dv, v, v);
        x_dup[t][c][r] = dv;
    }
    // stage h0 (duplicated)
    for (int i = tid; i < 16 * H_DIM; i += 1024) {
        int r = i & 15;
        int k = i >> 4;
        float v = h0[(size_t)(p0 + r) * H_DIM + k];
        ull dv; PKAB(dv, v, v);
        h_dup[0][k][r] = dv;
    }
    // c (only kh=0 uses it)
    float c_reg[4];
#pragma unroll
    for (int p = 0; p < 4; p++)
        c_reg[p] = c0[(size_t)(p0 + 4 * ty + p) * H_DIM + ch];
    ulonglong2 bi;
    if (kh == 0) bi = *(const ulonglong2*)&d_bsum2[ch * 4];
    else { bi.x = 0ull; bi.y = 0ull; }
    __syncthreads();

    const ulonglong2* wt2 = (const ulonglong2*)d_wt2;   // idx k*128 + ch
    const ulonglong2* wi2 = (const ulonglong2*)d_wit2;
    int ridx = ty * 128 + ch;
    int kbR = kh * 64;
    int kbI = kh * 32;

    for (int t = 0; t < T_STEPS; t++) {
        int cur = t & 1, nxt = cur ^ 1;
        ull acc[4][2];
#pragma unroll
        for (int p = 0; p < 4; p++) { acc[p][0] = bi.x; acc[p][1] = bi.y; }
        // recurrent: 64 of K=128
#pragma unroll 4
        for (int k = 0; k < 64; k++) {
            int kk = kbR + k;
            ulonglong2 wv = wt2[kk * 128 + ch];
            ulonglong2 h01 = *(const ulonglong2*)&h_dup[cur][kk][4 * ty];
            ulonglong2 h23 = *(const ulonglong2*)&h_dup[cur][kk][4 * ty + 2];
            FMA2(acc[0][0], h01.x, wv.x, acc[0][0]);
            FMA2(acc[0][1], h01.x, wv.y, acc[0][1]);
            FMA2(acc[1][0], h01.y, wv.x, acc[1][0]);
            FMA2(acc[1][1], h01.y, wv.y, acc[1][1]);
            FMA2(acc[2][0], h23.x, wv.x, acc[2][0]);
            FMA2(acc[2][1], h23.x, wv.y, acc[2][1]);
            FMA2(acc[3][0], h23.y, wv.x, acc[3][0]);
            FMA2(acc[3][1], h23.y, wv.y, acc[3][1]);
        }
        // input: 32 of K=64
#pragma unroll 4
        for (int k = 0; k < 32; k++) {
            int kk = kbI + k;
            ulonglong2 wv = wi2[kk * 128 + ch];
            ulonglong2 x01 = *(const ulonglong2*)&x_dup[t][kk][4 * ty];
            ulonglong2 x23 = *(const ulonglong2*)&x_dup[t][kk][4 * ty + 2];
            FMA2(acc[0][0], x01.x, wv.x, acc[0][0]);
            FMA2(acc[0][1], x01.x, wv.y, acc[0][1]);
            FMA2(acc[1][0], x01.y, wv.x, acc[1][0]);
            FMA2(acc[1][1], x01.y, wv.y, acc[1][1]);
            FMA2(acc[2][0], x23.x, wv.x, acc[2][0]);
            FMA2(acc[2][1], x23.x, wv.y, acc[2][1]);
            FMA2(acc[3][0], x23.y, wv.x, acc[3][0]);
            FMA2(acc[3][1], x23.y, wv.y, acc[3][1]);
        }
        if (kh) {
#pragma unroll
            for (int p = 0; p < 4; p++) {
                red[p * 2 + 0][ridx] = acc[p][0];
                red[p * 2 + 1][ridx] = acc[p][1];
            }
        }
        __syncthreads();
        if (!kh) {
#pragma unroll
            for (int p = 0; p < 4; p++) {
                ADD2(acc[p][0], acc[p][0], red[p * 2 + 0][ridx]);
                ADD2(acc[p][1], acc[p][1], red[p * 2 + 1][ridx]);
                float iv, fv, gv, ov;
                UNPK2(iv, fv, acc[p][0]);
                UNPK2(gv, ov, acc[p][1]);
                float cn = sigf(fv) * c_reg[p] + sigf(iv) * tanh_f(gv);
                c_reg[p] = cn;
                float hv = sigf(ov) * tanh_f(cn);
                ull dv; PKAB(dv, hv, hv);
                h_dup[nxt][ch][4 * ty + p] = dv;
            }
        }
        __syncthreads();
    }
    // final h in buffer 0 (T_STEPS even)
    for (int i = tid; i < 16 * H_DIM; i += 1024) {
        int k = i & 127;
        int r = i >> 7;
        float v = __uint_as_float((unsigned)(h_dup[0][k][r] & 0xffffffffull));
        d_h [(size_t)(p0 + r) * H_DIM + k] = v;
        d_th[(size_t)(p0 + r) * H_DIM + k] = tanh_f(v);
    }
}

// ---------------- gate MLP (position-only), standalone ----------------
__global__ __launch_bounds__(256) void gateMLP(
    const float* __restrict__ goal, const float* __restrict__ action,
    const float* __restrict__ W_dist, const float* __restrict__ b_dist,
    const float* __restrict__ W_gate, const float* __restrict__ b_gate)
{
    __shared__ __align__(16) float t_sh[GRP_N * DD_DIM];       // 8KB
    __shared__ __align__(16) float s_sh[2 * DD_DIM];
    __shared__ __align__(16) float r_sh[2 * GRP_N * DD_DIM];   // 16KB
    __shared__ float pax[GRP_N], pay[GRP_N], pgx[GRP_N], pgy[GRP_N];

    int tid = threadIdx.x;
    int b = blockIdx.x;
    int g  = b >> 4;
    int ip = b & 15;
    int half = tid >> 7;
    int c    = tid & 127;
    int i_loc = 2 * ip + half;
    int p = g * GRP_N + i_loc;

    if (tid < GRP_N) {
        int q = g * GRP_N + tid;
        pax[tid] = action[q * 2 + 0]; pay[tid] = action[q * 2 + 1];
        pgx[tid] = goal[q * 2 + 0];   pgy[tid] = goal[q * 2 + 1];
    }
    __syncthreads();
    for (int idx = tid; idx < GRP_N * DD_DIM; idx += 256) {
        int j = idx >> 6, d = idx & 63;
        float t = fmaf(pax[j], W_dist[4 * 64 + d],
                  fmaf(pay[j], W_dist[5 * 64 + d],
                  fmaf(pgx[j], W_dist[6 * 64 + d],
                       pgy[j] * W_dist[7 * 64 + d])));
        t_sh[idx] = t;
    }
    if (tid < 2 * DD_DIM) {
        int hh = tid >> 6, d = tid & 63;
        int il = 2 * ip + hh;
        float s = b_dist[d];
        s = fmaf(pax[il], W_dist[0 * 64 + d], s);
        s = fmaf(pay[il], W_dist[1 * 64 + d], s);
        s = fmaf(pgx[il], W_dist[2 * 64 + d], s);
        s = fmaf(pgy[il], W_dist[3 * 64 + d], s);
        s_sh[tid] = s;
    }
    __syncthreads();
    for (int idx = tid; idx < 2 * GRP_N * DD_DIM; idx += 256) {
        int hh = idx >> 11, jd = idx & 2047;
        r_sh[idx] = fmaxf(s_sh[hh * 64 + (jd & 63)] + t_sh[jd], 0.f);
    }
    __syncthreads();

    float bg = b_gate[c];
    const float* rbase = r_sh + half * GRP_N * DD_DIM;
    float* gout = d_gate + (size_t)p * GRP_N * H_DIM;
#pragma unroll
    for (int jt = 0; jt < 4; jt++) {
        int j0 = jt * 8;
        ull acc2[8];
#pragma unroll
        for (int jj = 0; jj < 8; jj++) acc2[jj] = 0ull;
        for (int d0 = 0; d0 < DD_DIM; d0 += 4) {
            float w0 = W_gate[(d0 + 0) * H_DIM + c];
            float w1 = W_gate[(d0 + 1) * H_DIM + c];
            float w2 = W_gate[(d0 + 2) * H_DIM + c];
            float w3 = W_gate[(d0 + 3) * H_DIM + c];
            ull ww0, ww1;
            PKAB(ww0, w0, w1);
            PKAB(ww1, w2, w3);
#pragma unroll
            for (int jj = 0; jj < 8; jj++) {
                ulonglong2 rv = *(const ulonglong2*)&rbase[(j0 + jj) * DD_DIM + d0];
                FMA2(acc2[jj], rv.x, ww0, acc2[jj]);
                FMA2(acc2[jj], rv.y, ww1, acc2[jj]);
            }
        }
#pragma unroll
        for (int jj = 0; jj < 8; jj++) {
            float lo, hi;
            UNPK2(lo, hi, acc2[jj]);
            gout[(j0 + jj) * H_DIM + c] = sigf(lo + hi + bg);
        }
    }
}

// ---------------- KERNEL B: h-dependent GAT ----------------
__global__ __launch_bounds__(256) void gatB(const float* __restrict__ goal_hidden)
{
    __shared__ __align__(16) float gth[2 * GRP_N * H_DIM];  // 32KB
    __shared__ float ah_sh[2][H_DIM];
    __shared__ float sdot[2][NH][GRP_N];
    __shared__ float alpha[2][NH][GRP_N + 1];
    __shared__ float hsu[2][NH], hsv[2][NH];

    int tid = threadIdx.x;
    int b = blockIdx.x;
    int g  = b >> 4;
    int ip = b & 15;
    int half = tid >> 7;
    int c    = tid & 127;
    int i_loc = 2 * ip + half;
    int p = g * GRP_N + i_loc;

    float ahc = d_h[(size_t)p * H_DIM + c];
    float ghc = goal_hidden[(size_t)p * H_DIM + c];
    ah_sh[half][c] = ahc;

    {
        const float* gp = d_gate + (size_t)p * GRP_N * H_DIM;
        float* dst = gth + half * GRP_N * H_DIM;
#pragma unroll 4
        for (int j = 0; j < GRP_N; j++) {
            float v = gp[j * H_DIM + c] * d_th[(size_t)(g * GRP_N + j) * H_DIM + c];
            dst[j * H_DIM + c] = (j == i_loc) ? ghc : v;
        }
    }
    __syncthreads();

    {
        int t128 = tid & 127, w = t128 >> 5, lane = t128 & 31;
        const float* uh = d_uv + w * H_DIM;
        const float* vh = d_uv + NH * H_DIM + w * H_DIM;
        float u4[4], v4[4], a4[4];
#pragma unroll
        for (int k = 0; k < 4; k++) {
            int cc = lane + 32 * k;
            u4[k] = uh[cc]; v4[k] = vh[cc];
            a4[k] = ah_sh[half][cc];
        }
        float su = 0.f, sv = 0.f;
#pragma unroll
        for (int k = 0; k < 4; k++) { su = fmaf(a4[k], u4[k], su); sv = fmaf(a4[k], v4[k], sv); }
#pragma unroll
        for (int o = 16; o; o >>= 1) {
            su += __shfl_xor_sync(0xffffffffu, su, o);
            sv += __shfl_xor_sync(0xffffffffu, sv, o);
        }
        if (lane == 0) { hsu[half][w] = su; hsv[half][w] = sv; }
        const float* src = gth + half * GRP_N * H_DIM;
        for (int j = 0; j < GRP_N; j++) {
            float s = 0.f;
#pragma unroll
            for (int k = 0; k < 4; k++)
                s = fmaf(src[j * H_DIM + lane + 32 * k], v4[k], s);
#pragma unroll
            for (int o = 16; o; o >>= 1) s += __shfl_xor_sync(0xffffffffu, s, o);
            if (lane == 0) sdot[half][w][j] = s;
        }
    }
    __syncthreads();

    if (tid < 8) {
        int hh = tid >> 2, h = tid & 3;
        float su = hsu[hh][h], sv = hsv[hh][h];
        float sc[GRP_N + 1];
        float s0 = su + sv;
        sc[0] = (s0 >= 0.f) ? s0 : 0.2f * s0;
        float mx = sc[0];
#pragma unroll
        for (int j = 0; j < GRP_N; j++) {
            float s = su + sdot[hh][h][j];
            s = (s >= 0.f) ? s : 0.2f * s;
            sc[j + 1] = s;
            mx = fmaxf(mx, s);
        }
        float sum = 0.f;
#pragma unroll
        for (int k = 0; k <= GRP_N; k++) { sc[k] = __expf(sc[k] - mx); sum += sc[k]; }
        float inv = __fdividef(1.f, sum);
#pragma unroll
        for (int k = 0; k <= GRP_N; k++) alpha[hh][h][k] = sc[k] * inv;
    }
    __syncthreads();

    // m_cat[p][h*128+c]
    {
        float macc[NH];
#pragma unroll
        for (int h = 0; h < NH; h++) macc[h] = alpha[half][h][0] * ahc;
        const float* src = gth + half * GRP_N * H_DIM;
#pragma unroll 4
        for (int j = 0; j < GRP_N; j++) {
            float gval = src[j * H_DIM + c];
#pragma unroll
            for (int h = 0; h < NH; h++)
                macc[h] = fmaf(alpha[half][h][j + 1], gval, macc[h]);
        }
#pragma unroll
        for (int h = 0; h < NH; h++)
            d_m[(size_t)p * G4H + h * H_DIM + c] = macc[h];
    }
}

// ---------------- g3: out = relu(0.25 * m_cat @ w_cat) + bias ----------------
__global__ __launch_bounds__(256) void g3_kernel(
    const float* __restrict__ gat_w, const float* __restrict__ gat_bias,
    float* __restrict__ out)
{
    __shared__ __align__(16) float m_sh[16][G4H];   // 32KB
    int tid = threadIdx.x;
    int tx = tid & 63, ty = tid >> 6;
    int p0 = blockIdx.x * 16;

    {
        float4* dst = (float4*)&m_sh[0][0];
        const float4* src = (const float4*)&d_m[(size_t)p0 * G4H];
        for (int i = tid; i < 2048; i += 256) dst[i] = src[i];
    }
    __syncthreads();

    ull acc[4];
#pragma unroll
    for (int p = 0; p < 4; p++) acc[p] = 0ull;
#pragma unroll 8
    for (int k = 0; k < G4H; k++) {
        ull wv = *(const ull*)&gat_w[(size_t)k * H_DIM + 2 * tx];
        ull mp[4];
#pragma unroll
        for (int p = 0; p < 4; p++) PK2(mp[p], m_sh[4 * ty + p][k]);
#pragma unroll
        for (int p = 0; p < 4; p++) FMA2(acc[p], mp[p], wv, acc[p]);
    }
    float b0 = gat_bias[2 * tx], b1 = gat_bias[2 * tx + 1];
#pragma unroll
    for (int p = 0; p < 4; p++) {
        float lo, hi;
        UNPK2(lo, hi, acc[p]);
        float2 o2;
        o2.x = fmaxf(0.25f * lo, 0.f) + b0;
        o2.y = fmaxf(0.25f * hi, 0.f) + b1;
        *(float2*)&out[(size_t)(p0 + 4 * ty + p) * H_DIM + 2 * tx] = o2;
    }
}

// ---------------- host ----------------
extern "C" void kernel_launch(void* const* d_in, const int* in_sizes, int n_in,
                              void* d_out, int out_size)
{
    const float* obs         = (const float*)d_in[0];
    const float* goal_hidden = (const float*)d_in[1];
    const float* goal        = (const float*)d_in[2];
    const float* action      = (const float*)d_in[3];
    const float* h0          = (const float*)d_in[4];
    const float* c0          = (const float*)d_in[5];
    const float* W_emb       = (const float*)d_in[6];
    const float* b_emb       = (const float*)d_in[7];
    const float* W_ih        = (const float*)d_in[8];
    const float* W_hh        = (const float*)d_in[9];
    const float* b_ih        = (const float*)d_in[10];
    const float* b_hh        = (const float*)d_in[11];
    const float* W_dist      = (const float*)d_in[12];
    const float* b_dist      = (const float*)d_in[13];
    const float* W_gate      = (const float*)d_in[14];
    const float* b_gate      = (const float*)d_in[15];
    const float* gat_w       = (const float*)d_in[16];
    const float* gat_a       = (const float*)d_in[17];
    const float* gat_bias    = (const float*)d_in[18];
    float* out = (float*)d_out;

    const int LSTM_SMEM = 36864 + 65536 + 32768;   // h_dup + x_dup + red = 132KB
    cudaFuncSetAttribute(lstm1024, cudaFuncAttributeMaxDynamicSharedMemorySize, LSTM_SMEM);

    {
        int total = H_DIM * G4H + D_IN * G4H + G4H;
        prep_kernel<<<(total + 255) / 256, 256>>>(W_hh, W_ih, b_ih, b_hh);
    }
    uv_kernel<<<256, 128>>>(gat_w, gat_a);
    gateMLP<<<1024, 256>>>(goal, action, W_dist, b_dist, W_gate, b_gate);

    lstm1024<<<N_PED / 16, 1024, LSTM_SMEM>>>(h0, c0, obs, W_emb, b_emb);

    gatB<<<1024, 256>>>(goal_hidden);
    g3_kernel<<<N_PED / 16, 256>>>(gat_w, gat_bias, out);
}